// round 14
// baseline (speedup 1.0000x reference)
#include <cuda_runtime.h>
#include <cstdint>

#define NN      12000
#define HID     32
#define TSTEPS  50
#define TM      128
#define NBLK    94               // ceil(12000/128) — one CTA per row block
#define NCHUNK  375              // full K = 12000 / 32
#define NSTAGES 8
#define BOFF    16384            // B region offset within a stage
#define BSTRIDE 160              // B row stride in bytes (conflict-free, no swizzle)
#define STAGE_BYTES (BOFF + 32 * BSTRIDE)    // 21504
#define SMEM_REQ (NSTAGES * STAGE_BYTES)     // 172032 (occ 1)

__device__ float g_supp[NN * HID];   // support, ROW-major [node][h], tf32-rounded

// ---------------------------------------------------------------------------
// Kernel 1: support = [z | a_t] @ W, row-major, direct register->GMEM stores.
// (round-13 variant: 7.2us measured)
// ---------------------------------------------------------------------------
__global__ void support_kernel(const float* __restrict__ t,
                               const float* __restrict__ z,
                               const float* __restrict__ treat,
                               const float* __restrict__ W) {
    __shared__ float Ws[33 * 32];
    int tid = threadIdx.x;
    for (int i = tid; i < 33 * 32; i += blockDim.x) Ws[i] = W[i];
    __syncthreads();

    int a_idx = (int)(t[0] * (float)(TSTEPS - 1));
    a_idx = min(max(a_idx, 0), TSTEPS - 1);

    int lane = tid & 31;
    int warp = tid >> 5;
    int row0 = blockIdx.x * 32 + warp * 4;   // grid = 375, 375*32 == 12000

    float zv[4], acc[4];
#pragma unroll
    for (int j = 0; j < 4; j++) {
        int row = row0 + j;
        zv[j]  = z[row * 32 + lane];
        acc[j] = treat[row * TSTEPS + a_idx] * Ws[32 * 32 + lane];
    }
#pragma unroll
    for (int k = 0; k < 32; k++) {
        float w = Ws[k * 32 + lane];
#pragma unroll
        for (int j = 0; j < 4; j++) {
            float zk = __shfl_sync(0xffffffffu, zv[j], k);
            acc[j] = fmaf(zk, w, acc[j]);
        }
    }
#pragma unroll
    for (int j = 0; j < 4; j++) {
        uint32_t bits;
        asm("cvt.rna.tf32.f32 %0, %1;" : "=r"(bits) : "f"(acc[j]));
        g_supp[(row0 + j) * 32 + lane] = __uint_as_float(bits);
    }
}

// ---------------------------------------------------------------------------
// Stage loads. A: swizzled, line-complete warp-ops. B: one contiguous 4KB row
// block of row-major g_supp.
// ---------------------------------------------------------------------------
__device__ __forceinline__ void load_A(uint32_t sbase, const float* __restrict__ adj,
                                       int row0, int gk, int tid) {
    int q  = tid & 7;
    int rb = tid >> 3;
#pragma unroll
    for (int i = 0; i < 4; i++) {
        int r = i * 32 + rb;
        const float* src = adj + (long long)(row0 + r) * NN + gk + q * 4;
        uint32_t dst = sbase + r * 128 + (uint32_t)((q ^ (r & 7)) << 4);
        int sz = (row0 + r < NN) ? 16 : 0;
        asm volatile("cp.async.cg.shared.global.L2::256B [%0], [%1], 16, %2;\n"
                     :: "r"(dst), "l"(src), "r"(sz));
    }
}

__device__ __forceinline__ void load_B(uint32_t sbase, int gk, int tid) {
    int q  = tid & 7;
    int rb = tid >> 3;
    const float* src = g_supp + (long long)(gk + rb) * HID + q * 4;
    uint32_t dst = sbase + BOFF + rb * BSTRIDE + q * 16;
    asm volatile("cp.async.cg.shared.global [%0], [%1], 16;\n"
                 :: "r"(dst), "l"(src));
}

// ---------------------------------------------------------------------------
// Kernel 2: tf32 mma.sync GEMM, full-K per CTA (no split-K), fused bias+relu.
// 94 CTAs, occ 1, 8-stage cp.async ring (168KB smem).
// ---------------------------------------------------------------------------
__global__ void __launch_bounds__(256, 1)
gemm_mma_kernel(const float* __restrict__ adj,
                const float* __restrict__ bias,
                float* __restrict__ out) {
    extern __shared__ char dsm[];
    uint32_t sbase0 = (uint32_t)__cvta_generic_to_shared(dsm);
    int tid  = threadIdx.x;
    int warp = tid >> 5;
    int lane = tid & 31;
    int g    = lane >> 2;
    int tg   = lane & 3;

    int row0 = blockIdx.x * TM;

    float acc[4][4];
#pragma unroll
    for (int n = 0; n < 4; n++)
#pragma unroll
        for (int i = 0; i < 4; i++) acc[n][i] = 0.f;

    const uint32_t aoff = (uint32_t)(warp * 16 + g) * 128 + tg * 4;
    const uint32_t boff = (uint32_t)BOFF + tg * BSTRIDE + g * 4;

#pragma unroll
    for (int p = 0; p < NSTAGES - 1; p++) {
        uint32_t sb = sbase0 + p * STAGE_BYTES;
        load_A(sb, adj, row0, p * 32, tid);
        load_B(sb, p * 32, tid);
        asm volatile("cp.async.commit_group;\n" ::: "memory");
    }

    int s = 0;                      // current stage index (avoids % in loop)
    for (int c = 0; c < NCHUNK; c++) {
        asm volatile("cp.async.wait_group %0;\n" :: "n"(NSTAGES - 2) : "memory");
        __syncthreads();

        if (c + NSTAGES - 1 < NCHUNK) {
            int ps = s + (NSTAGES - 1); if (ps >= NSTAGES) ps -= NSTAGES;
            uint32_t sb = sbase0 + ps * STAGE_BYTES;
            load_A(sb, adj, row0, (c + NSTAGES - 1) * 32, tid);
            load_B(sb, (c + NSTAGES - 1) * 32, tid);
        }
        asm volatile("cp.async.commit_group;\n" ::: "memory");

        const char* st = dsm + s * STAGE_BYTES;
        if (++s == NSTAGES) s = 0;
#pragma unroll
        for (int ks = 0; ks < 4; ks++) {
            uint32_t q0 = (uint32_t)(((2 * ks) ^ g) << 4);
            uint32_t q1 = (uint32_t)(((2 * ks + 1) ^ g) << 4);

            uint32_t a0 = *(const uint32_t*)(st + aoff + q0);
            uint32_t a2 = *(const uint32_t*)(st + aoff + q1);
            uint32_t a1 = *(const uint32_t*)(st + aoff + 1024 + q0);
            uint32_t a3 = *(const uint32_t*)(st + aoff + 1024 + q1);
#pragma unroll
            for (int nt = 0; nt < 4; nt++) {
                uint32_t b0 = *(const uint32_t*)(st + boff + ks * (8 * BSTRIDE) +
                                                 nt * 32);
                uint32_t b1 = *(const uint32_t*)(st + boff + ks * (8 * BSTRIDE) +
                                                 nt * 32 + 4 * BSTRIDE);
                asm volatile(
                    "mma.sync.aligned.m16n8k8.row.col.f32.tf32.tf32.f32 "
                    "{%0,%1,%2,%3}, {%4,%5,%6,%7}, {%8,%9}, {%0,%1,%2,%3};\n"
                    : "+f"(acc[nt][0]), "+f"(acc[nt][1]),
                      "+f"(acc[nt][2]), "+f"(acc[nt][3])
                    : "r"(a0), "r"(a1), "r"(a2), "r"(a3), "r"(b0), "r"(b1));
            }
        }
    }

    // epilogue: bias + relu, write final output directly
    int r_lo = row0 + warp * 16 + g;
    int r_hi = r_lo + 8;
#pragma unroll
    for (int nt = 0; nt < 4; nt++) {
        int colb = nt * 8 + 2 * tg;
        float2 bb = *(const float2*)(bias + colb);
        if (r_lo < NN) {
            float2 v;
            v.x = fmaxf(acc[nt][0] + bb.x, 0.f);
            v.y = fmaxf(acc[nt][1] + bb.y, 0.f);
            *(float2*)(out + (long long)r_lo * HID + colb) = v;
        }
        if (r_hi < NN) {
            float2 v;
            v.x = fmaxf(acc[nt][2] + bb.x, 0.f);
            v.y = fmaxf(acc[nt][3] + bb.y, 0.f);
            *(float2*)(out + (long long)r_hi * HID + colb) = v;
        }
    }
}

// ---------------------------------------------------------------------------
extern "C" void kernel_launch(void* const* d_in, const int* in_sizes, int n_in,
                              void* d_out, int out_size) {
    (void)in_sizes; (void)n_in; (void)out_size;
    const float* t     = (const float*)d_in[0];
    const float* z     = (const float*)d_in[1];
    const float* adj   = (const float*)d_in[2];
    const float* treat = (const float*)d_in[3];
    const float* W     = (const float*)d_in[4];
    const float* b     = (const float*)d_in[5];
    float* out = (float*)d_out;

    cudaFuncSetAttribute(gemm_mma_kernel,
                         cudaFuncAttributeMaxDynamicSharedMemorySize, SMEM_REQ);

    support_kernel<<<NN / 32, 256>>>(t, z, treat, W);
    gemm_mma_kernel<<<NBLK, 256, SMEM_REQ>>>(adj, b, out);
}

// round 15
// speedup vs baseline: 1.3935x; 1.3935x over previous
#include <cuda_runtime.h>
#include <cstdint>

#define NN      12000
#define HID     32
#define TSTEPS  50
#define TM      128
#define KSPLIT  3
#define KITEM   4000             // K per work item (KSPLIT*KITEM == NN)
#define NCHUNK  125              // KITEM / 32
#define NBLK    94               // ceil(12000/128)
#define NITEMS  (NBLK * KSPLIT)  // 282 CTAs, one item each
#define NSTAGES 5
#define STAGE_BYTES 20480        // A: 128*32*4 = 16384  +  B: 32*32*4 = 4096
#define SMEM_REQ (NSTAGES * STAGE_BYTES)

__device__ float g_suppT[HID * NN];           // support^T: [32][12000], tf32-rounded
__device__ float g_part[KSPLIT * NN * HID];   // split-K partials (deterministic)

// ---------------------------------------------------------------------------
// Kernel 1: support = [z | a_t] @ W, transposed + tf32-rounded output.
// ---------------------------------------------------------------------------
__global__ void support_kernel(const float* __restrict__ t,
                               const float* __restrict__ z,
                               const float* __restrict__ treat,
                               const float* __restrict__ W) {
    __shared__ float Ws[33 * 32];
    __shared__ float S[32][33];    // stride 33 -> conflict-free transpose
    int tid = threadIdx.x;
    for (int i = tid; i < 33 * 32; i += blockDim.x) Ws[i] = W[i];
    __syncthreads();

    int a_idx = (int)(t[0] * (float)(TSTEPS - 1));
    a_idx = min(max(a_idx, 0), TSTEPS - 1);

    int lane = tid & 31;
    int warp = tid >> 5;
    int row0 = blockIdx.x * 32;         // grid = 375, 375*32 == 12000
    int r0   = warp * 4;                // warp's 4 rows within block

    float zv[4], acc[4];
#pragma unroll
    for (int j = 0; j < 4; j++) {
        int row = row0 + r0 + j;
        zv[j]  = z[row * 32 + lane];
        acc[j] = treat[row * TSTEPS + a_idx] * Ws[32 * 32 + lane];
    }
#pragma unroll
    for (int k = 0; k < 32; k++) {
        float w = Ws[k * 32 + lane];
#pragma unroll
        for (int j = 0; j < 4; j++) {
            float zk = __shfl_sync(0xffffffffu, zv[j], k);
            acc[j] = fmaf(zk, w, acc[j]);
        }
    }
#pragma unroll
    for (int j = 0; j < 4; j++) {
        uint32_t bits;
        asm("cvt.rna.tf32.f32 %0, %1;" : "=r"(bits) : "f"(acc[j]));
        S[r0 + j][lane] = __uint_as_float(bits);
    }
    __syncthreads();

    // coalesced transposed store: 1024 elems, 4 per thread
#pragma unroll
    for (int j = 0; j < 4; j++) {
        int idx = tid + 256 * j;
        int col = idx >> 5;
        int r   = idx & 31;
        g_suppT[col * NN + row0 + r] = S[r][col];
    }
}

// ---------------------------------------------------------------------------
// Kernel 2: tf32 mma.sync GEMM. 256 thr, 8 warps x (m16,n32), 5-stage cp.async.
// Load lane map is LINE-COMPLETE per warp-op: row = tid>>3, chunk = tid&7, so
// every touched 128B line gets all 8x16B requests in one warp-op (whole
// sectors -> no doubled LTS transactions).
// ---------------------------------------------------------------------------
__device__ __forceinline__ void load_stage(char* stage, const float* __restrict__ adj,
                                           int row0, int gk, int tid) {
    int q  = tid & 7;              // 16B chunk within 128B row-chunk
    int rb = tid >> 3;             // 0..31
    uint32_t sbase = (uint32_t)__cvta_generic_to_shared(stage);

    // A: 128 rows x 128 B; 4 iterations of 32 rows, each warp-op = 4 full lines
#pragma unroll
    for (int i = 0; i < 4; i++) {
        int r = i * 32 + rb;
        const float* src = adj + (long long)(row0 + r) * NN + gk + q * 4;
        uint32_t dst = sbase + r * 128 + (uint32_t)((q ^ (r & 7)) << 4);
        int sz = (row0 + r < NN) ? 16 : 0;
        asm volatile("cp.async.cg.shared.global.L2::256B [%0], [%1], 16, %2;\n"
                     :: "r"(dst), "l"(src), "r"(sz));
    }
    // B: 32 cols x 128 B; one 16B chunk per thread, warp-op = 4 full lines
    {
        int c = rb;
        const float* src = g_suppT + (long long)c * NN + gk + q * 4;
        uint32_t dst = sbase + 16384 + c * 128 + (uint32_t)((q ^ (c & 7)) << 4);
        asm volatile("cp.async.cg.shared.global.L2::256B [%0], [%1], 16;\n"
                     :: "r"(dst), "l"(src));
    }
}

__global__ void __launch_bounds__(256, 2)
gemm_mma_kernel(const float* __restrict__ adj) {
    extern __shared__ char dsm[];
    int tid  = threadIdx.x;
    int warp = tid >> 5;
    int lane = tid & 31;
    int g    = lane >> 2;    // groupID
    int tg   = lane & 3;     // threadID in group

    int blk  = blockIdx.x / KSPLIT;
    int kc   = blockIdx.x - blk * KSPLIT;
    int row0 = blk * TM;
    int k0   = kc * KITEM;

    float acc[4][4];
#pragma unroll
    for (int n = 0; n < 4; n++)
#pragma unroll
        for (int i = 0; i < 4; i++) acc[n][i] = 0.f;

    const uint32_t aoff = (uint32_t)(warp * 16 + g) * 128 + tg * 4;
    const uint32_t boff = 16384u + (uint32_t)g * 128 + tg * 4;

#pragma unroll
    for (int p = 0; p < NSTAGES - 1; p++) {
        load_stage(dsm + p * STAGE_BYTES, adj, row0, k0 + p * 32, tid);
        asm volatile("cp.async.commit_group;\n" ::: "memory");
    }

    for (int c = 0; c < NCHUNK; c++) {
        asm volatile("cp.async.wait_group %0;\n" :: "n"(NSTAGES - 2) : "memory");
        __syncthreads();

        if (c + NSTAGES - 1 < NCHUNK)
            load_stage(dsm + ((c + NSTAGES - 1) % NSTAGES) * STAGE_BYTES, adj,
                       row0, k0 + (c + NSTAGES - 1) * 32, tid);
        asm volatile("cp.async.commit_group;\n" ::: "memory");

        const char* st = dsm + (c % NSTAGES) * STAGE_BYTES;
#pragma unroll
        for (int ks = 0; ks < 4; ks++) {
            uint32_t q0 = (uint32_t)(((2 * ks) ^ g) << 4);
            uint32_t q1 = (uint32_t)(((2 * ks + 1) ^ g) << 4);

            uint32_t a0 = *(const uint32_t*)(st + aoff + q0);
            uint32_t a2 = *(const uint32_t*)(st + aoff + q1);
            uint32_t a1 = *(const uint32_t*)(st + aoff + 1024 + q0);
            uint32_t a3 = *(const uint32_t*)(st + aoff + 1024 + q1);
#pragma unroll
            for (int nt = 0; nt < 4; nt++) {
                uint32_t b0 = *(const uint32_t*)(st + boff + nt * 1024 + q0);
                uint32_t b1 = *(const uint32_t*)(st + boff + nt * 1024 + q1);
                asm volatile(
                    "mma.sync.aligned.m16n8k8.row.col.f32.tf32.tf32.f32 "
                    "{%0,%1,%2,%3}, {%4,%5,%6,%7}, {%8,%9}, {%0,%1,%2,%3};\n"
                    : "+f"(acc[nt][0]), "+f"(acc[nt][1]),
                      "+f"(acc[nt][2]), "+f"(acc[nt][3])
                    : "r"(a0), "r"(a1), "r"(a2), "r"(a3), "r"(b0), "r"(b1));
            }
        }
    }

    float* part = g_part + (long long)kc * (NN * HID);
    int r_lo = row0 + warp * 16 + g;
    int r_hi = r_lo + 8;
#pragma unroll
    for (int nt = 0; nt < 4; nt++) {
        int colb = nt * 8 + 2 * tg;
        if (r_lo < NN)
            *(float2*)(part + (long long)r_lo * HID + colb) =
                make_float2(acc[nt][0], acc[nt][1]);
        if (r_hi < NN)
            *(float2*)(part + (long long)r_hi * HID + colb) =
                make_float2(acc[nt][2], acc[nt][3]);
    }
}

// ---------------------------------------------------------------------------
// Kernel 3: out = relu(sum_kc part[kc] + b)
// ---------------------------------------------------------------------------
__global__ void reduce_relu_kernel(float* __restrict__ out,
                                   const float* __restrict__ b) {
    int i4 = blockIdx.x * blockDim.x + threadIdx.x;
    if (i4 >= NN * HID / 4) return;
    const float4* p = (const float4*)g_part;
    float4 s = ((const float4*)b)[i4 & 7];
#pragma unroll
    for (int kc = 0; kc < KSPLIT; kc++) {
        float4 v = p[(long long)kc * (NN * HID / 4) + i4];
        s.x += v.x; s.y += v.y; s.z += v.z; s.w += v.w;
    }
    float4 r;
    r.x = fmaxf(s.x, 0.f);
    r.y = fmaxf(s.y, 0.f);
    r.z = fmaxf(s.z, 0.f);
    r.w = fmaxf(s.w, 0.f);
    ((float4*)out)[i4] = r;
}

// ---------------------------------------------------------------------------
extern "C" void kernel_launch(void* const* d_in, const int* in_sizes, int n_in,
                              void* d_out, int out_size) {
    (void)in_sizes; (void)n_in; (void)out_size;
    const float* t     = (const float*)d_in[0];
    const float* z     = (const float*)d_in[1];
    const float* adj   = (const float*)d_in[2];
    const float* treat = (const float*)d_in[3];
    const float* W     = (const float*)d_in[4];
    const float* b     = (const float*)d_in[5];
    float* out = (float*)d_out;

    cudaFuncSetAttribute(gemm_mma_kernel,
                         cudaFuncAttributeMaxDynamicSharedMemorySize, SMEM_REQ);

    support_kernel<<<NN / 32, 256>>>(t, z, treat, W);
    gemm_mma_kernel<<<NITEMS, 256, SMEM_REQ>>>(adj);
    reduce_relu_kernel<<<(NN * HID / 4 + 255) / 256, 256>>>(out, b);
}